// round 3
// baseline (speedup 1.0000x reference)
#include <cuda_runtime.h>
#include <math.h>

#define D_    1024
#define H_    16
#define HD_   64
#define S_    2048
#define B_    4
#define T_    (B_*S_)      // 8192 tokens
#define DFF_  4096
#define SIXD_ 6144

// ---------------- scratch (static device globals; no allocation) ----------------
__device__ float g_mod [B_*SIXD_];                     // 96 KB
__device__ float g_xn  [(size_t)T_*D_];                // 32 MB
__device__ float g_qkv [(size_t)T_*3*D_];              // 96 MB
__device__ float g_q   [(size_t)B_*H_*S_*HD_];         // 32 MB
__device__ float g_k   [(size_t)B_*H_*S_*HD_];         // 32 MB
__device__ float g_v   [(size_t)B_*H_*S_*HD_];         // 32 MB
__device__ float g_attn[(size_t)T_*D_];                // 32 MB
__device__ float g_x2  [(size_t)T_*D_];                // 32 MB
__device__ float g_h   [(size_t)T_*DFF_];              // 128 MB

// ---------------- adaLN modulation: mod[b][j] = c[b]·ada_W[:,j] + ada_b[j] ------
__global__ void mod_kernel(const float* __restrict__ c,
                           const float* __restrict__ adaW,
                           const float* __restrict__ adab,
                           float* __restrict__ mod)
{
    int b = blockIdx.y;
    int j = blockIdx.x * 256 + threadIdx.x;
    __shared__ float cs[D_];
    for (int i = threadIdx.x; i < D_; i += 256) cs[i] = c[b*D_ + i];
    __syncthreads();
    float acc = adab[j];
#pragma unroll 4
    for (int k = 0; k < D_; k++)
        acc = fmaf(cs[k], adaW[(size_t)k*SIXD_ + j], acc);
    mod[b*SIXD_ + j] = acc;
}

// ---------------- LayerNorm + modulate (shift/scale chunks of mod) --------------
__global__ void ln_mod_kernel(const float* __restrict__ x,
                              const float* __restrict__ w,
                              const float* __restrict__ mod,
                              float* __restrict__ out,
                              int sh_off, int sc_off)
{
    int t = blockIdx.x;
    int b = t / S_;
    int tid = threadIdx.x;          // 256 threads, 4 elems each
    float4 v = ((const float4*)(x + (size_t)t*D_))[tid];
    float s  = v.x + v.y + v.z + v.w;
    float sq = v.x*v.x + v.y*v.y + v.z*v.z + v.w*v.w;
#pragma unroll
    for (int o = 16; o > 0; o >>= 1) {
        s  += __shfl_xor_sync(0xffffffffu, s,  o);
        sq += __shfl_xor_sync(0xffffffffu, sq, o);
    }
    __shared__ float ss[8], ssq[8];
    int warp = tid >> 5, lane = tid & 31;
    if (lane == 0) { ss[warp] = s; ssq[warp] = sq; }
    __syncthreads();
    if (warp == 0) {
        s  = (lane < 8) ? ss[lane]  : 0.f;
        sq = (lane < 8) ? ssq[lane] : 0.f;
#pragma unroll
        for (int o = 4; o > 0; o >>= 1) {
            s  += __shfl_xor_sync(0xffffffffu, s,  o);
            sq += __shfl_xor_sync(0xffffffffu, sq, o);
        }
        if (lane == 0) { ss[0] = s; ssq[0] = sq; }
    }
    __syncthreads();
    s = ss[0]; sq = ssq[0];
    float mu   = s  * (1.f/D_);
    float var  = sq * (1.f/D_) - mu*mu;
    float rsig = rsqrtf(var + 1e-5f);

    const float* modb = mod + b*SIXD_;
    float4 wv  = ((const float4*)w)[tid];
    float4 shv = ((const float4*)(modb + sh_off))[tid];
    float4 scv = ((const float4*)(modb + sc_off))[tid];
    float4 r;
    r.x = fmaf((v.x-mu)*rsig*wv.x, (1.f+scv.x), shv.x);
    r.y = fmaf((v.y-mu)*rsig*wv.y, (1.f+scv.y), shv.y);
    r.z = fmaf((v.z-mu)*rsig*wv.z, (1.f+scv.z), shv.z);
    r.w = fmaf((v.w-mu)*rsig*wv.w, (1.f+scv.w), shv.w);
    ((float4*)(out + (size_t)t*D_))[tid] = r;
}

// ---------------- RMSNorm(q,k) + RoPE + layout to [bh][s][hd] --------------------
// 512 threads/block = 16 warps, warp == head; lane owns elems (lane, lane+32)
__global__ void qk_rope_kernel(const float* __restrict__ qkv,
                               const float* __restrict__ cosp,
                               const float* __restrict__ sinp,
                               const float* __restrict__ qw,
                               const float* __restrict__ kw,
                               float* __restrict__ Q,
                               float* __restrict__ K,
                               float* __restrict__ V)
{
    int t = blockIdx.x;
    int s = t % S_;
    int b = t / S_;
    int h    = threadIdx.x >> 5;
    int lane = threadIdx.x & 31;
    const float* base = qkv + (size_t)t*3*D_ + h*HD_;
    float q0 = base[lane],        q1 = base[lane+32];
    float k0 = base[D_+lane],     k1 = base[D_+lane+32];
    float v0 = base[2*D_+lane],   v1 = base[2*D_+lane+32];

    float qs = q0*q0 + q1*q1;
    float ks = k0*k0 + k1*k1;
#pragma unroll
    for (int o = 16; o > 0; o >>= 1) {
        qs += __shfl_xor_sync(0xffffffffu, qs, o);
        ks += __shfl_xor_sync(0xffffffffu, ks, o);
    }
    float qr = rsqrtf(qs*(1.f/HD_) + 1e-6f);
    float kr = rsqrtf(ks*(1.f/HD_) + 1e-6f);
    q0 *= qr*qw[lane];  q1 *= qr*qw[lane+32];
    k0 *= kr*kw[lane];  k1 *= kr*kw[lane+32];

    float c0 = cosp[s*HD_+lane], c1 = cosp[s*HD_+lane+32];
    float n0 = sinp[s*HD_+lane], n1 = sinp[s*HD_+lane+32];
    // rope: out[i<32] = x*cos - x[i+32]*sin ; out[i>=32] = x*cos + x[i-32]*sin
    float qo0 = (q0*c0 - q1*n0) * 0.125f;   // fold 1/sqrt(HD) into q
    float qo1 = (q1*c1 + q0*n1) * 0.125f;
    float ko0 =  k0*c0 - k1*n0;
    float ko1 =  k1*c1 + k0*n1;

    size_t o = ((size_t)(b*H_ + h)*S_ + s)*HD_;
    Q[o+lane] = qo0;  Q[o+lane+32] = qo1;
    K[o+lane] = ko0;  K[o+lane+32] = ko1;
    V[o+lane] = v0;   V[o+lane+32] = v1;
}

// ---------------- flash attention: 64 q-rows per CTA, online softmax -------------
#define ATTN_PAD 65
#define ATTN_SMEM (4*64*ATTN_PAD*4)

__global__ void attn_kernel(const float* __restrict__ Q,
                            const float* __restrict__ K,
                            const float* __restrict__ V,
                            float* __restrict__ out)
{
    extern __shared__ float sm[];
    float* Qs = sm;
    float* Ks = Qs + 64*ATTN_PAD;
    float* Vs = Ks + 64*ATTN_PAD;
    float* Ps = Vs + 64*ATTN_PAD;

    int bh = blockIdx.y;
    int qt = blockIdx.x;
    int tid = threadIdx.x;       // 256
    int ty = tid >> 4, tx = tid & 15;

    const float* Qb = Q + ((size_t)bh*S_ + qt*64)*HD_;
    for (int i = tid; i < 1024; i += 256) {
        int r = i >> 4, c = (i & 15) * 4;
        float4 v = *(const float4*)(Qb + r*HD_ + c);
        Qs[r*ATTN_PAD+c]=v.x; Qs[r*ATTN_PAD+c+1]=v.y;
        Qs[r*ATTN_PAD+c+2]=v.z; Qs[r*ATTN_PAD+c+3]=v.w;
    }
    float m[4], l[4], o[4][4];
#pragma unroll
    for (int i = 0; i < 4; i++) {
        m[i] = -1e30f; l[i] = 0.f;
#pragma unroll
        for (int j = 0; j < 4; j++) o[i][j] = 0.f;
    }
    __syncthreads();

    for (int kt = 0; kt < S_/64; kt++) {
        const float* Kb = K + ((size_t)bh*S_ + kt*64)*HD_;
        const float* Vb = V + ((size_t)bh*S_ + kt*64)*HD_;
        for (int i = tid; i < 1024; i += 256) {
            int r = i >> 4, c = (i & 15) * 4;
            float4 kv = *(const float4*)(Kb + r*HD_ + c);
            Ks[r*ATTN_PAD+c]=kv.x; Ks[r*ATTN_PAD+c+1]=kv.y;
            Ks[r*ATTN_PAD+c+2]=kv.z; Ks[r*ATTN_PAD+c+3]=kv.w;
            float4 vv = *(const float4*)(Vb + r*HD_ + c);
            Vs[r*ATTN_PAD+c]=vv.x; Vs[r*ATTN_PAD+c+1]=vv.y;
            Vs[r*ATTN_PAD+c+2]=vv.z; Vs[r*ATTN_PAD+c+3]=vv.w;
        }
        __syncthreads();

        float sacc[4][4] = {};
#pragma unroll 4
        for (int kk = 0; kk < 64; kk++) {
            float rq[4], rk[4];
#pragma unroll
            for (int i = 0; i < 4; i++) rq[i] = Qs[(ty*4+i)*ATTN_PAD + kk];
#pragma unroll
            for (int j = 0; j < 4; j++) rk[j] = Ks[(tx*4+j)*ATTN_PAD + kk];
#pragma unroll
            for (int i = 0; i < 4; i++)
#pragma unroll
                for (int j = 0; j < 4; j++)
                    sacc[i][j] = fmaf(rq[i], rk[j], sacc[i][j]);
        }

        // online softmax (rows split across the 16 tx lanes of each ty group)
#pragma unroll
        for (int i = 0; i < 4; i++) {
            float rmax = fmaxf(fmaxf(sacc[i][0], sacc[i][1]),
                               fmaxf(sacc[i][2], sacc[i][3]));
#pragma unroll
            for (int off = 8; off > 0; off >>= 1)
                rmax = fmaxf(rmax, __shfl_xor_sync(0xffffffffu, rmax, off));
            float mnew  = fmaxf(m[i], rmax);
            float alpha = __expf(m[i] - mnew);
            float rsum = 0.f;
#pragma unroll
            for (int j = 0; j < 4; j++) {
                float p = __expf(sacc[i][j] - mnew);
                sacc[i][j] = p; rsum += p;
            }
#pragma unroll
            for (int off = 8; off > 0; off >>= 1)
                rsum += __shfl_xor_sync(0xffffffffu, rsum, off);
            l[i] = l[i]*alpha + rsum;
            m[i] = mnew;
#pragma unroll
            for (int j = 0; j < 4; j++) o[i][j] *= alpha;
        }

#pragma unroll
        for (int i = 0; i < 4; i++)
#pragma unroll
            for (int j = 0; j < 4; j++)
                Ps[(ty*4+i)*ATTN_PAD + tx*4+j] = sacc[i][j];
        __syncthreads();

#pragma unroll 4
        for (int kk = 0; kk < 64; kk++) {
            float rp[4], rv[4];
#pragma unroll
            for (int i = 0; i < 4; i++) rp[i] = Ps[(ty*4+i)*ATTN_PAD + kk];
#pragma unroll
            for (int j = 0; j < 4; j++) rv[j] = Vs[kk*ATTN_PAD + tx*4+j];
#pragma unroll
            for (int i = 0; i < 4; i++)
#pragma unroll
                for (int j = 0; j < 4; j++)
                    o[i][j] = fmaf(rp[i], rv[j], o[i][j]);
        }
        __syncthreads();
    }

    int b = bh >> 4, h = bh & 15;
#pragma unroll
    for (int i = 0; i < 4; i++) {
        float inv = 1.f / l[i];
        int srow = qt*64 + ty*4 + i;
        float* op = out + ((size_t)(b*S_ + srow))*D_ + h*HD_ + tx*4;
#pragma unroll
        for (int j = 0; j < 4; j++) op[j] = o[i][j]*inv;
    }
}

// ---------------- tiled SGEMM with fused epilogues -------------------------------
__device__ __forceinline__ float gelu_t(float x)
{
    float x3 = x*x*x;
    return 0.5f*x*(1.f + tanhf(0.7978845608028654f*(x + 0.044715f*x3)));
}

// MODE 0: C = acc
// MODE 1: C = res + gate*acc                     (attn out-proj + residual)
// MODE 2: C = gelu(acc + bias)                   (MLP up)
// MODE 3: C = res + gate*(acc + bias)            (MLP down + residual)
template <int MODE>
__global__ __launch_bounds__(256)
void sgemm_kernel(const float* __restrict__ A, const float* __restrict__ Bm,
                  float* __restrict__ C, int N, int K,
                  const float* __restrict__ res, const float* __restrict__ bias,
                  const float* __restrict__ mod, int gate_off)
{
    const int BM = 128, BN = 128, BK = 8;
    __shared__ float As[BK*BM];
    __shared__ float Bs[BK*BN];
    int tid = threadIdx.x;
    int tr = tid >> 4, tc = tid & 15;
    int arow = tid >> 1,  acol = (tid & 1) * 4;
    int brow = tid >> 5,  bcol = (tid & 31) * 4;
    const float* Ap = A  + (size_t)blockIdx.y * BM * K;
    const float* Bp = Bm + blockIdx.x * BN;

    float acc[8][8] = {};
    for (int k0 = 0; k0 < K; k0 += BK) {
        float4 av = *(const float4*)(Ap + (size_t)arow*K + k0 + acol);
        As[(acol+0)*BM + arow] = av.x;
        As[(acol+1)*BM + arow] = av.y;
        As[(acol+2)*BM + arow] = av.z;
        As[(acol+3)*BM + arow] = av.w;
        *(float4*)(Bs + brow*BN + bcol) =
            *(const float4*)(Bp + (size_t)(k0 + brow)*N + bcol);
        __syncthreads();
#pragma unroll
        for (int kk = 0; kk < BK; kk++) {
            float rM[8], rN[8];
            *(float4*)(rM)   = *(float4*)(As + kk*BM + tr*8);
            *(float4*)(rM+4) = *(float4*)(As + kk*BM + tr*8 + 4);
            *(float4*)(rN)   = *(float4*)(Bs + kk*BN + tc*8);
            *(float4*)(rN+4) = *(float4*)(Bs + kk*BN + tc*8 + 4);
#pragma unroll
            for (int i = 0; i < 8; i++)
#pragma unroll
                for (int j = 0; j < 8; j++)
                    acc[i][j] = fmaf(rM[i], rN[j], acc[i][j]);
        }
        __syncthreads();
    }

    int row0 = blockIdx.y*BM + tr*8;
    int col0 = blockIdx.x*BN + tc*8;
#pragma unroll
    for (int i = 0; i < 8; i++) {
        int row = row0 + i;
        const float* modb = (MODE == 1 || MODE == 3)
                          ? (mod + (row >> 11)*SIXD_ + gate_off) : nullptr;
#pragma unroll
        for (int j = 0; j < 8; j++) {
            int col = col0 + j;
            float v = acc[i][j];
            if (MODE == 1) v = res[(size_t)row*N + col] + modb[col]*v;
            else if (MODE == 2) v = gelu_t(v + bias[col]);
            else if (MODE == 3) v = res[(size_t)row*N + col]
                                  + modb[col]*(v + bias[col]);
            C[(size_t)row*N + col] = v;
        }
    }
}

// ---------------- launch ---------------------------------------------------------
extern "C" void kernel_launch(void* const* d_in, const int* in_sizes, int n_in,
                              void* d_out, int out_size)
{
    const float* x      = (const float*)d_in[0];
    const float* cosp   = (const float*)d_in[1];
    const float* sinp   = (const float*)d_in[2];
    const float* c      = (const float*)d_in[3];
    const float* n1w    = (const float*)d_in[4];
    const float* Wqkv   = (const float*)d_in[5];
    const float* Wout   = (const float*)d_in[6];
    const float* qw     = (const float*)d_in[7];
    const float* kw     = (const float*)d_in[8];
    const float* n2w    = (const float*)d_in[9];
    const float* W1     = (const float*)d_in[10];
    const float* b1     = (const float*)d_in[11];
    const float* W2     = (const float*)d_in[12];
    const float* b2     = (const float*)d_in[13];
    const float* adaW   = (const float*)d_in[14];
    const float* adab   = (const float*)d_in[15];
    float* out = (float*)d_out;

    float *p_mod, *p_xn, *p_qkv, *p_q, *p_k, *p_v, *p_attn, *p_x2, *p_h;
    cudaGetSymbolAddress((void**)&p_mod,  g_mod);
    cudaGetSymbolAddress((void**)&p_xn,   g_xn);
    cudaGetSymbolAddress((void**)&p_qkv,  g_qkv);
    cudaGetSymbolAddress((void**)&p_q,    g_q);
    cudaGetSymbolAddress((void**)&p_k,    g_k);
    cudaGetSymbolAddress((void**)&p_v,    g_v);
    cudaGetSymbolAddress((void**)&p_attn, g_attn);
    cudaGetSymbolAddress((void**)&p_x2,   g_x2);
    cudaGetSymbolAddress((void**)&p_h,    g_h);

    cudaFuncSetAttribute(attn_kernel,
                         cudaFuncAttributeMaxDynamicSharedMemorySize, ATTN_SMEM);

    // 1. adaLN modulation
    mod_kernel<<<dim3(SIXD_/256, B_), 256>>>(c, adaW, adab, p_mod);
    // 2. LN1 + modulate
    ln_mod_kernel<<<T_, 256>>>(x, n1w, p_mod, p_xn, 0, D_);
    // 3. QKV projection
    sgemm_kernel<0><<<dim3(3*D_/128, T_/128), 256>>>(p_xn, Wqkv, p_qkv,
                                                     3*D_, D_, nullptr, nullptr,
                                                     nullptr, 0);
    // 4. qk-RMSNorm + RoPE + relayout (+ fold softmax scale into q)
    qk_rope_kernel<<<T_, 512>>>(p_qkv, cosp, sinp, qw, kw, p_q, p_k, p_v);
    // 5. attention
    attn_kernel<<<dim3(S_/64, B_*H_), 256, ATTN_SMEM>>>(p_q, p_k, p_v, p_attn);
    // 6. out-proj + gated residual  (gate = g_msa at offset 2D)
    sgemm_kernel<1><<<dim3(D_/128, T_/128), 256>>>(p_attn, Wout, p_x2,
                                                   D_, D_, x, nullptr,
                                                   p_mod, 2*D_);
    // 7. LN2 + modulate (shift 3D, scale 4D)
    ln_mod_kernel<<<T_, 256>>>(p_x2, n2w, p_mod, p_xn, 3*D_, 4*D_);
    // 8. MLP up + gelu
    sgemm_kernel<2><<<dim3(DFF_/128, T_/128), 256>>>(p_xn, W1, p_h,
                                                     DFF_, D_, nullptr, b1,
                                                     nullptr, 0);
    // 9. MLP down + gated residual (gate = g_mlp at offset 5D)
    sgemm_kernel<3><<<dim3(D_/128, T_/128), 256>>>(p_h, W2, out,
                                                   D_, DFF_, p_x2, b2,
                                                   p_mod, 5*D_);
}

// round 4
// speedup vs baseline: 1.8377x; 1.8377x over previous
#include <cuda_runtime.h>
#include <math.h>
#include <stdint.h>

#define D_    1024
#define H_    16
#define HD_   64
#define S_    2048
#define B_    4
#define T_    (B_*S_)      // 8192 tokens
#define DFF_  4096
#define SIXD_ 6144

// ---------------- scratch (static device globals; no allocation) ----------------
__device__ float g_mod [B_*SIXD_];                     // 96 KB
__device__ float g_xn  [(size_t)T_*D_];                // 32 MB
__device__ float g_qkv [(size_t)T_*3*D_];              // 96 MB
__device__ float g_q   [(size_t)B_*H_*S_*HD_];         // 32 MB
__device__ float g_k   [(size_t)B_*H_*S_*HD_];         // 32 MB
__device__ float g_v   [(size_t)B_*H_*S_*HD_];         // 32 MB
__device__ float g_attn[(size_t)T_*D_];                // 32 MB
__device__ float g_x2  [(size_t)T_*D_];                // 32 MB
__device__ float g_h   [(size_t)T_*DFF_];              // 128 MB

// ---------------- adaLN modulation ------------------------------------------------
__global__ void mod_kernel(const float* __restrict__ c,
                           const float* __restrict__ adaW,
                           const float* __restrict__ adab,
                           float* __restrict__ mod)
{
    int b = blockIdx.y;
    int j = blockIdx.x * 256 + threadIdx.x;
    __shared__ float cs[D_];
    for (int i = threadIdx.x; i < D_; i += 256) cs[i] = c[b*D_ + i];
    __syncthreads();
    float acc = adab[j];
#pragma unroll 4
    for (int k = 0; k < D_; k++)
        acc = fmaf(cs[k], adaW[(size_t)k*SIXD_ + j], acc);
    mod[b*SIXD_ + j] = acc;
}

// ---------------- LayerNorm + modulate --------------------------------------------
__global__ void ln_mod_kernel(const float* __restrict__ x,
                              const float* __restrict__ w,
                              const float* __restrict__ mod,
                              float* __restrict__ out,
                              int sh_off, int sc_off)
{
    int t = blockIdx.x;
    int b = t / S_;
    int tid = threadIdx.x;
    float4 v = ((const float4*)(x + (size_t)t*D_))[tid];
    float s  = v.x + v.y + v.z + v.w;
    float sq = v.x*v.x + v.y*v.y + v.z*v.z + v.w*v.w;
#pragma unroll
    for (int o = 16; o > 0; o >>= 1) {
        s  += __shfl_xor_sync(0xffffffffu, s,  o);
        sq += __shfl_xor_sync(0xffffffffu, sq, o);
    }
    __shared__ float ss[8], ssq[8];
    int warp = tid >> 5, lane = tid & 31;
    if (lane == 0) { ss[warp] = s; ssq[warp] = sq; }
    __syncthreads();
    if (warp == 0) {
        s  = (lane < 8) ? ss[lane]  : 0.f;
        sq = (lane < 8) ? ssq[lane] : 0.f;
#pragma unroll
        for (int o = 4; o > 0; o >>= 1) {
            s  += __shfl_xor_sync(0xffffffffu, s,  o);
            sq += __shfl_xor_sync(0xffffffffu, sq, o);
        }
        if (lane == 0) { ss[0] = s; ssq[0] = sq; }
    }
    __syncthreads();
    s = ss[0]; sq = ssq[0];
    float mu   = s  * (1.f/D_);
    float var  = sq * (1.f/D_) - mu*mu;
    float rsig = rsqrtf(var + 1e-5f);

    const float* modb = mod + b*SIXD_;
    float4 wv  = ((const float4*)w)[tid];
    float4 shv = ((const float4*)(modb + sh_off))[tid];
    float4 scv = ((const float4*)(modb + sc_off))[tid];
    float4 r;
    r.x = fmaf((v.x-mu)*rsig*wv.x, (1.f+scv.x), shv.x);
    r.y = fmaf((v.y-mu)*rsig*wv.y, (1.f+scv.y), shv.y);
    r.z = fmaf((v.z-mu)*rsig*wv.z, (1.f+scv.z), shv.z);
    r.w = fmaf((v.w-mu)*rsig*wv.w, (1.f+scv.w), shv.w);
    ((float4*)(out + (size_t)t*D_))[tid] = r;
}

// ---------------- RMSNorm(q,k) + RoPE + relayout ----------------------------------
__global__ void qk_rope_kernel(const float* __restrict__ qkv,
                               const float* __restrict__ cosp,
                               const float* __restrict__ sinp,
                               const float* __restrict__ qw,
                               const float* __restrict__ kw,
                               float* __restrict__ Q,
                               float* __restrict__ K,
                               float* __restrict__ V)
{
    int t = blockIdx.x;
    int s = t % S_;
    int b = t / S_;
    int h    = threadIdx.x >> 5;
    int lane = threadIdx.x & 31;
    const float* base = qkv + (size_t)t*3*D_ + h*HD_;
    float q0 = base[lane],        q1 = base[lane+32];
    float k0 = base[D_+lane],     k1 = base[D_+lane+32];
    float v0 = base[2*D_+lane],   v1 = base[2*D_+lane+32];

    float qs = q0*q0 + q1*q1;
    float ks = k0*k0 + k1*k1;
#pragma unroll
    for (int o = 16; o > 0; o >>= 1) {
        qs += __shfl_xor_sync(0xffffffffu, qs, o);
        ks += __shfl_xor_sync(0xffffffffu, ks, o);
    }
    float qr = rsqrtf(qs*(1.f/HD_) + 1e-6f);
    float kr = rsqrtf(ks*(1.f/HD_) + 1e-6f);
    q0 *= qr*qw[lane];  q1 *= qr*qw[lane+32];
    k0 *= kr*kw[lane];  k1 *= kr*kw[lane+32];

    float c0 = cosp[s*HD_+lane], c1 = cosp[s*HD_+lane+32];
    float n0 = sinp[s*HD_+lane], n1 = sinp[s*HD_+lane+32];
    float qo0 = (q0*c0 - q1*n0) * 0.125f;
    float qo1 = (q1*c1 + q0*n1) * 0.125f;
    float ko0 =  k0*c0 - k1*n0;
    float ko1 =  k1*c1 + k0*n1;

    size_t o = ((size_t)(b*H_ + h)*S_ + s)*HD_;
    Q[o+lane] = qo0;  Q[o+lane+32] = qo1;
    K[o+lane] = ko0;  K[o+lane+32] = ko1;
    V[o+lane] = v0;   V[o+lane+32] = v1;
}

// ---------------- flash attention (unchanged, fp32 SIMT) --------------------------
#define ATTN_PAD 65
#define ATTN_SMEM (4*64*ATTN_PAD*4)

__global__ void attn_kernel(const float* __restrict__ Q,
                            const float* __restrict__ K,
                            const float* __restrict__ V,
                            float* __restrict__ out)
{
    extern __shared__ float sm[];
    float* Qs = sm;
    float* Ks = Qs + 64*ATTN_PAD;
    float* Vs = Ks + 64*ATTN_PAD;
    float* Ps = Vs + 64*ATTN_PAD;

    int bh = blockIdx.y;
    int qt = blockIdx.x;
    int tid = threadIdx.x;
    int ty = tid >> 4, tx = tid & 15;

    const float* Qb = Q + ((size_t)bh*S_ + qt*64)*HD_;
    for (int i = tid; i < 1024; i += 256) {
        int r = i >> 4, c = (i & 15) * 4;
        float4 v = *(const float4*)(Qb + r*HD_ + c);
        Qs[r*ATTN_PAD+c]=v.x; Qs[r*ATTN_PAD+c+1]=v.y;
        Qs[r*ATTN_PAD+c+2]=v.z; Qs[r*ATTN_PAD+c+3]=v.w;
    }
    float m[4], l[4], o[4][4];
#pragma unroll
    for (int i = 0; i < 4; i++) {
        m[i] = -1e30f; l[i] = 0.f;
#pragma unroll
        for (int j = 0; j < 4; j++) o[i][j] = 0.f;
    }
    __syncthreads();

    for (int kt = 0; kt < S_/64; kt++) {
        const float* Kb = K + ((size_t)bh*S_ + kt*64)*HD_;
        const float* Vb = V + ((size_t)bh*S_ + kt*64)*HD_;
        for (int i = tid; i < 1024; i += 256) {
            int r = i >> 4, c = (i & 15) * 4;
            float4 kv = *(const float4*)(Kb + r*HD_ + c);
            Ks[r*ATTN_PAD+c]=kv.x; Ks[r*ATTN_PAD+c+1]=kv.y;
            Ks[r*ATTN_PAD+c+2]=kv.z; Ks[r*ATTN_PAD+c+3]=kv.w;
            float4 vv = *(const float4*)(Vb + r*HD_ + c);
            Vs[r*ATTN_PAD+c]=vv.x; Vs[r*ATTN_PAD+c+1]=vv.y;
            Vs[r*ATTN_PAD+c+2]=vv.z; Vs[r*ATTN_PAD+c+3]=vv.w;
        }
        __syncthreads();

        float sacc[4][4] = {};
#pragma unroll 4
        for (int kk = 0; kk < 64; kk++) {
            float rq[4], rk[4];
#pragma unroll
            for (int i = 0; i < 4; i++) rq[i] = Qs[(ty*4+i)*ATTN_PAD + kk];
#pragma unroll
            for (int j = 0; j < 4; j++) rk[j] = Ks[(tx*4+j)*ATTN_PAD + kk];
#pragma unroll
            for (int i = 0; i < 4; i++)
#pragma unroll
                for (int j = 0; j < 4; j++)
                    sacc[i][j] = fmaf(rq[i], rk[j], sacc[i][j]);
        }

#pragma unroll
        for (int i = 0; i < 4; i++) {
            float rmax = fmaxf(fmaxf(sacc[i][0], sacc[i][1]),
                               fmaxf(sacc[i][2], sacc[i][3]));
#pragma unroll
            for (int off = 8; off > 0; off >>= 1)
                rmax = fmaxf(rmax, __shfl_xor_sync(0xffffffffu, rmax, off));
            float mnew  = fmaxf(m[i], rmax);
            float alpha = __expf(m[i] - mnew);
            float rsum = 0.f;
#pragma unroll
            for (int j = 0; j < 4; j++) {
                float p = __expf(sacc[i][j] - mnew);
                sacc[i][j] = p; rsum += p;
            }
#pragma unroll
            for (int off = 8; off > 0; off >>= 1)
                rsum += __shfl_xor_sync(0xffffffffu, rsum, off);
            l[i] = l[i]*alpha + rsum;
            m[i] = mnew;
#pragma unroll
            for (int j = 0; j < 4; j++) o[i][j] *= alpha;
        }

#pragma unroll
        for (int i = 0; i < 4; i++)
#pragma unroll
            for (int j = 0; j < 4; j++)
                Ps[(ty*4+i)*ATTN_PAD + tx*4+j] = sacc[i][j];
        __syncthreads();

#pragma unroll 4
        for (int kk = 0; kk < 64; kk++) {
            float rp[4], rv[4];
#pragma unroll
            for (int i = 0; i < 4; i++) rp[i] = Ps[(ty*4+i)*ATTN_PAD + kk];
#pragma unroll
            for (int j = 0; j < 4; j++) rv[j] = Vs[kk*ATTN_PAD + tx*4+j];
#pragma unroll
            for (int i = 0; i < 4; i++)
#pragma unroll
                for (int j = 0; j < 4; j++)
                    o[i][j] = fmaf(rp[i], rv[j], o[i][j]);
        }
        __syncthreads();
    }

    int b = bh >> 4, h = bh & 15;
#pragma unroll
    for (int i = 0; i < 4; i++) {
        float inv = 1.f / l[i];
        int srow = qt*64 + ty*4 + i;
        float* op = out + ((size_t)(b*S_ + srow))*D_ + h*HD_ + tx*4;
#pragma unroll
        for (int j = 0; j < 4; j++) op[j] = o[i][j]*inv;
    }
}

// ================= TF32 tensor-core GEMM with fused epilogues =====================
// Block 128x128, BK=16, 256 threads = 8 warps (2 M x 4 N), warp tile 64x32.
// mma.sync.aligned.m16n8k8.row.col.f32.tf32.tf32.f32, fp32 accumulate.
// Smem layouts chosen for conflict-free fragment loads:
//   As[m][k], pitch 20 words  -> a-frag banks (20r+c)%32 bijective over 32 lanes
//   Bs[k][n], pitch 136 words -> b-frag banks (8k+n)%32  bijective over 32 lanes
#define GBM 128
#define GBN 128
#define GBK 16
#define AP  20
#define BP  136

__device__ __forceinline__ void cp_async16(float* smem, const float* gmem)
{
    uint32_t sa = (uint32_t)__cvta_generic_to_shared(smem);
    asm volatile("cp.async.cg.shared.global [%0], [%1], 16;\n"
                 :: "r"(sa), "l"(gmem));
}
#define CP_COMMIT() asm volatile("cp.async.commit_group;\n" ::: "memory")
#define CP_WAIT1()  asm volatile("cp.async.wait_group 1;\n" ::: "memory")

__device__ __forceinline__ uint32_t f2tf(float x)
{
    uint32_t r;
    asm("cvt.rna.tf32.f32 %0, %1;\n" : "=r"(r) : "f"(x));
    return r;
}

__device__ __forceinline__ void mma_tf32(float* c, const uint32_t* a,
                                         const uint32_t* b)
{
    asm volatile("mma.sync.aligned.m16n8k8.row.col.f32.tf32.tf32.f32 "
                 "{%0,%1,%2,%3}, {%4,%5,%6,%7}, {%8,%9}, {%0,%1,%2,%3};\n"
                 : "+f"(c[0]), "+f"(c[1]), "+f"(c[2]), "+f"(c[3])
                 : "r"(a[0]), "r"(a[1]), "r"(a[2]), "r"(a[3]),
                   "r"(b[0]), "r"(b[1]));
}

__device__ __forceinline__ float gelu_t(float x)
{
    float x3 = x*x*x;
    return 0.5f*x*(1.f + tanhf(0.7978845608028654f*(x + 0.044715f*x3)));
}

// MODE 0: C = acc
// MODE 1: C = res + gate*acc
// MODE 2: C = gelu(acc + bias)
// MODE 3: C = res + gate*(acc + bias)
template <int MODE>
__global__ __launch_bounds__(256)
void mma_gemm(const float* __restrict__ A, const float* __restrict__ Bm,
              float* __restrict__ C, int N, int K,
              const float* __restrict__ res, const float* __restrict__ bias,
              const float* __restrict__ mod, int gate_off)
{
    __shared__ float As[2][GBM*AP];   // 20480 B
    __shared__ float Bs[2][GBK*BP];   // 17408 B

    int tid  = threadIdx.x;
    int warp = tid >> 5, lane = tid & 31;
    int wm   = (warp >> 2) * 64;      // warp M origin within block
    int wn   = (warp & 3)  * 32;      // warp N origin within block
    int gid  = lane >> 2;             // 0..7
    int tig  = lane & 3;              // 0..3

    const float* Ap = A  + (size_t)blockIdx.y * GBM * K;
    const float* Bp = Bm + blockIdx.x * GBN;

    // global->smem assignment: 2x float4 for A, 2x float4 for B per thread
    int ar = tid >> 1;                // A row 0..127
    int ac = (tid & 1) * 8;           // A k-col base {0,8}
    int bk = tid >> 4;                // B k-row 0..15
    int bn = (tid & 15) * 8;          // B n base

    float acc[4][4][4];
#pragma unroll
    for (int i = 0; i < 4; i++)
#pragma unroll
        for (int j = 0; j < 4; j++)
#pragma unroll
            for (int q = 0; q < 4; q++) acc[i][j][q] = 0.f;

    // prefetch stage 0
    {
        const float* ag = Ap + (size_t)ar*K + ac;
        cp_async16(&As[0][ar*AP + ac],     ag);
        cp_async16(&As[0][ar*AP + ac + 4], ag + 4);
        const float* bg = Bp + (size_t)bk*N + bn;
        cp_async16(&Bs[0][bk*BP + bn],     bg);
        cp_async16(&Bs[0][bk*BP + bn + 4], bg + 4);
    }
    CP_COMMIT();

    int buf = 0;
    for (int k0 = 0; k0 < K; k0 += GBK) {
        if (k0 + GBK < K) {
            const float* ag = Ap + (size_t)ar*K + (k0 + GBK) + ac;
            cp_async16(&As[buf^1][ar*AP + ac],     ag);
            cp_async16(&As[buf^1][ar*AP + ac + 4], ag + 4);
            const float* bg = Bp + (size_t)(k0 + GBK + bk)*N + bn;
            cp_async16(&Bs[buf^1][bk*BP + bn],     bg);
            cp_async16(&Bs[buf^1][bk*BP + bn + 4], bg + 4);
        }
        CP_COMMIT();
        CP_WAIT1();
        __syncthreads();

        const float* as = As[buf];
        const float* bs = Bs[buf];
#pragma unroll
        for (int kc = 0; kc < GBK; kc += 8) {
            uint32_t af[4][4], bf[4][2];
#pragma unroll
            for (int i = 0; i < 4; i++) {
                int r0 = wm + i*16 + gid;
                af[i][0] = f2tf(as[ r0     *AP + kc + tig]);
                af[i][1] = f2tf(as[(r0 + 8)*AP + kc + tig]);
                af[i][2] = f2tf(as[ r0     *AP + kc + tig + 4]);
                af[i][3] = f2tf(as[(r0 + 8)*AP + kc + tig + 4]);
            }
#pragma unroll
            for (int j = 0; j < 4; j++) {
                int n0 = wn + j*8 + gid;
                bf[j][0] = f2tf(bs[(kc + tig    )*BP + n0]);
                bf[j][1] = f2tf(bs[(kc + tig + 4)*BP + n0]);
            }
#pragma unroll
            for (int i = 0; i < 4; i++)
#pragma unroll
                for (int j = 0; j < 4; j++)
                    mma_tf32(acc[i][j], af[i], bf[j]);
        }
        __syncthreads();
        buf ^= 1;
    }

    // epilogue: c0,c1 = (row, 2t),(row, 2t+1); c2,c3 same cols at row+8
    int row_base = blockIdx.y*GBM + wm;
    int col_base = blockIdx.x*GBN + wn;
    int bb = (blockIdx.y * GBM) >> 11;      // batch (2048 rows per batch)
    const float* modb = (MODE == 1 || MODE == 3)
                      ? (mod + bb*SIXD_ + gate_off) : nullptr;
#pragma unroll
    for (int i = 0; i < 4; i++) {
        int r0 = row_base + i*16 + gid;
#pragma unroll
        for (int j = 0; j < 4; j++) {
            int c0 = col_base + j*8 + tig*2;
#pragma unroll
            for (int h = 0; h < 2; h++) {
                int row = r0 + h*8;
                float v0 = acc[i][j][h*2 + 0];
                float v1 = acc[i][j][h*2 + 1];
                if (MODE == 1) {
                    float2 rv = *(const float2*)(res + (size_t)row*N + c0);
                    v0 = rv.x + modb[c0    ]*v0;
                    v1 = rv.y + modb[c0 + 1]*v1;
                } else if (MODE == 2) {
                    v0 = gelu_t(v0 + bias[c0]);
                    v1 = gelu_t(v1 + bias[c0 + 1]);
                } else if (MODE == 3) {
                    float2 rv = *(const float2*)(res + (size_t)row*N + c0);
                    v0 = rv.x + modb[c0    ]*(v0 + bias[c0]);
                    v1 = rv.y + modb[c0 + 1]*(v1 + bias[c0 + 1]);
                }
                float2 st; st.x = v0; st.y = v1;
                *(float2*)(C + (size_t)row*N + c0) = st;
            }
        }
    }
}

// ---------------- launch ---------------------------------------------------------
extern "C" void kernel_launch(void* const* d_in, const int* in_sizes, int n_in,
                              void* d_out, int out_size)
{
    const float* x      = (const float*)d_in[0];
    const float* cosp   = (const float*)d_in[1];
    const float* sinp   = (const float*)d_in[2];
    const float* c      = (const float*)d_in[3];
    const float* n1w    = (const float*)d_in[4];
    const float* Wqkv   = (const float*)d_in[5];
    const float* Wout   = (const float*)d_in[6];
    const float* qw     = (const float*)d_in[7];
    const float* kw     = (const float*)d_in[8];
    const float* n2w    = (const float*)d_in[9];
    const float* W1     = (const float*)d_in[10];
    const float* b1     = (const float*)d_in[11];
    const float* W2     = (const float*)d_in[12];
    const float* b2     = (const float*)d_in[13];
    const float* adaW   = (const float*)d_in[14];
    const float* adab   = (const float*)d_in[15];
    float* out = (float*)d_out;

    float *p_mod, *p_xn, *p_qkv, *p_q, *p_k, *p_v, *p_attn, *p_x2, *p_h;
    cudaGetSymbolAddress((void**)&p_mod,  g_mod);
    cudaGetSymbolAddress((void**)&p_xn,   g_xn);
    cudaGetSymbolAddress((void**)&p_qkv,  g_qkv);
    cudaGetSymbolAddress((void**)&p_q,    g_q);
    cudaGetSymbolAddress((void**)&p_k,    g_k);
    cudaGetSymbolAddress((void**)&p_v,    g_v);
    cudaGetSymbolAddress((void**)&p_attn, g_attn);
    cudaGetSymbolAddress((void**)&p_x2,   g_x2);
    cudaGetSymbolAddress((void**)&p_h,    g_h);

    cudaFuncSetAttribute(attn_kernel,
                         cudaFuncAttributeMaxDynamicSharedMemorySize, ATTN_SMEM);

    // 1. adaLN modulation
    mod_kernel<<<dim3(SIXD_/256, B_), 256>>>(c, adaW, adab, p_mod);
    // 2. LN1 + modulate
    ln_mod_kernel<<<T_, 256>>>(x, n1w, p_mod, p_xn, 0, D_);
    // 3. QKV projection (tf32 mma)
    mma_gemm<0><<<dim3(3*D_/GBN, T_/GBM), 256>>>(p_xn, Wqkv, p_qkv,
                                                 3*D_, D_, nullptr, nullptr,
                                                 nullptr, 0);
    // 4. qk-RMSNorm + RoPE + relayout
    qk_rope_kernel<<<T_, 512>>>(p_qkv, cosp, sinp, qw, kw, p_q, p_k, p_v);
    // 5. attention
    attn_kernel<<<dim3(S_/64, B_*H_), 256, ATTN_SMEM>>>(p_q, p_k, p_v, p_attn);
    // 6. out-proj + gated residual (gate = g_msa at 2D)
    mma_gemm<1><<<dim3(D_/GBN, T_/GBM), 256>>>(p_attn, Wout, p_x2,
                                               D_, D_, x, nullptr,
                                               p_mod, 2*D_);
    // 7. LN2 + modulate (shift 3D, scale 4D)
    ln_mod_kernel<<<T_, 256>>>(p_x2, n2w, p_mod, p_xn, 3*D_, 4*D_);
    // 8. MLP up + gelu
    mma_gemm<2><<<dim3(DFF_/GBN, T_/GBM), 256>>>(p_xn, W1, p_h,
                                                 DFF_, D_, nullptr, b1,
                                                 nullptr, 0);
    // 9. MLP down + gated residual (gate = g_mlp at 5D)
    mma_gemm<3><<<dim3(D_/GBN, T_/GBM), 256>>>(p_h, W2, out,
                                               D_, DFF_, p_x2, b2,
                                               p_mod, 5*D_);
}

// round 6
// speedup vs baseline: 3.1681x; 1.7240x over previous
#include <cuda_runtime.h>
#include <math.h>
#include <stdint.h>

#define D_    1024
#define H_    16
#define HD_   64
#define S_    2048
#define B_    4
#define T_    (B_*S_)      // 8192 tokens
#define DFF_  4096
#define SIXD_ 6144

// ---------------- scratch (static device globals; no allocation) ----------------
__device__ float g_mod [B_*SIXD_];
__device__ float g_xn  [(size_t)T_*D_];
__device__ float g_qkv [(size_t)T_*3*D_];
__device__ float g_q   [(size_t)B_*H_*S_*HD_];
__device__ float g_k   [(size_t)B_*H_*S_*HD_];
__device__ float g_v   [(size_t)B_*H_*S_*HD_];
__device__ float g_attn[(size_t)T_*D_];
__device__ float g_x2  [(size_t)T_*D_];
__device__ float g_h   [(size_t)T_*DFF_];

// ---------------- async copy / mma helpers ---------------------------------------
__device__ __forceinline__ void cp_async16(float* smem, const float* gmem)
{
    uint32_t sa = (uint32_t)__cvta_generic_to_shared(smem);
    asm volatile("cp.async.cg.shared.global [%0], [%1], 16;\n"
                 :: "r"(sa), "l"(gmem));
}
#define CP_COMMIT()  asm volatile("cp.async.commit_group;\n" ::: "memory")
#define CP_WAIT1()   asm volatile("cp.async.wait_group 1;\n" ::: "memory")
#define CP_WAITALL() asm volatile("cp.async.wait_all;\n" ::: "memory")

__device__ __forceinline__ uint32_t f2tf(float x)
{
    uint32_t r;
    asm("cvt.rna.tf32.f32 %0, %1;\n" : "=r"(r) : "f"(x));
    return r;
}

__device__ __forceinline__ void mma_tf32(float* c, const uint32_t* a,
                                         const uint32_t* b)
{
    asm volatile("mma.sync.aligned.m16n8k8.row.col.f32.tf32.tf32.f32 "
                 "{%0,%1,%2,%3}, {%4,%5,%6,%7}, {%8,%9}, {%0,%1,%2,%3};\n"
                 : "+f"(c[0]), "+f"(c[1]), "+f"(c[2]), "+f"(c[3])
                 : "r"(a[0]), "r"(a[1]), "r"(a[2]), "r"(a[3]),
                   "r"(b[0]), "r"(b[1]));
}

// ---------------- adaLN modulation ------------------------------------------------
__global__ void mod_kernel(const float* __restrict__ c,
                           const float* __restrict__ adaW,
                           const float* __restrict__ adab,
                           float* __restrict__ mod)
{
    int b = blockIdx.y;
    int j = blockIdx.x * 256 + threadIdx.x;
    __shared__ float cs[D_];
    for (int i = threadIdx.x; i < D_; i += 256) cs[i] = c[b*D_ + i];
    __syncthreads();
    float acc = adab[j];
#pragma unroll 4
    for (int k = 0; k < D_; k++)
        acc = fmaf(cs[k], adaW[(size_t)k*SIXD_ + j], acc);
    mod[b*SIXD_ + j] = acc;
}

// ---------------- LayerNorm + modulate --------------------------------------------
__global__ void ln_mod_kernel(const float* __restrict__ x,
                              const float* __restrict__ w,
                              const float* __restrict__ mod,
                              float* __restrict__ out,
                              int sh_off, int sc_off)
{
    int t = blockIdx.x;
    int b = t / S_;
    int tid = threadIdx.x;
    float4 v = ((const float4*)(x + (size_t)t*D_))[tid];
    float s  = v.x + v.y + v.z + v.w;
    float sq = v.x*v.x + v.y*v.y + v.z*v.z + v.w*v.w;
#pragma unroll
    for (int o = 16; o > 0; o >>= 1) {
        s  += __shfl_xor_sync(0xffffffffu, s,  o);
        sq += __shfl_xor_sync(0xffffffffu, sq, o);
    }
    __shared__ float ss[8], ssq[8];
    int warp = tid >> 5, lane = tid & 31;
    if (lane == 0) { ss[warp] = s; ssq[warp] = sq; }
    __syncthreads();
    if (warp == 0) {
        s  = (lane < 8) ? ss[lane]  : 0.f;
        sq = (lane < 8) ? ssq[lane] : 0.f;
#pragma unroll
        for (int o = 4; o > 0; o >>= 1) {
            s  += __shfl_xor_sync(0xffffffffu, s,  o);
            sq += __shfl_xor_sync(0xffffffffu, sq, o);
        }
        if (lane == 0) { ss[0] = s; ssq[0] = sq; }
    }
    __syncthreads();
    s = ss[0]; sq = ssq[0];
    float mu   = s  * (1.f/D_);
    float var  = sq * (1.f/D_) - mu*mu;
    float rsig = rsqrtf(var + 1e-5f);

    const float* modb = mod + b*SIXD_;
    float4 wv  = ((const float4*)w)[tid];
    float4 shv = ((const float4*)(modb + sh_off))[tid];
    float4 scv = ((const float4*)(modb + sc_off))[tid];
    float4 r;
    r.x = fmaf((v.x-mu)*rsig*wv.x, (1.f+scv.x), shv.x);
    r.y = fmaf((v.y-mu)*rsig*wv.y, (1.f+scv.y), shv.y);
    r.z = fmaf((v.z-mu)*rsig*wv.z, (1.f+scv.z), shv.z);
    r.w = fmaf((v.w-mu)*rsig*wv.w, (1.f+scv.w), shv.w);
    ((float4*)(out + (size_t)t*D_))[tid] = r;
}

// ---------------- RMSNorm(q,k) + RoPE + relayout ----------------------------------
__global__ void qk_rope_kernel(const float* __restrict__ qkv,
                               const float* __restrict__ cosp,
                               const float* __restrict__ sinp,
                               const float* __restrict__ qw,
                               const float* __restrict__ kw,
                               float* __restrict__ Q,
                               float* __restrict__ K,
                               float* __restrict__ V)
{
    int t = blockIdx.x;
    int s = t % S_;
    int b = t / S_;
    int h    = threadIdx.x >> 5;
    int lane = threadIdx.x & 31;
    const float* base = qkv + (size_t)t*3*D_ + h*HD_;
    float q0 = base[lane],        q1 = base[lane+32];
    float k0 = base[D_+lane],     k1 = base[D_+lane+32];
    float v0 = base[2*D_+lane],   v1 = base[2*D_+lane+32];

    float qs = q0*q0 + q1*q1;
    float ks = k0*k0 + k1*k1;
#pragma unroll
    for (int o = 16; o > 0; o >>= 1) {
        qs += __shfl_xor_sync(0xffffffffu, qs, o);
        ks += __shfl_xor_sync(0xffffffffu, ks, o);
    }
    float qr = rsqrtf(qs*(1.f/HD_) + 1e-6f);
    float kr = rsqrtf(ks*(1.f/HD_) + 1e-6f);
    q0 *= qr*qw[lane];  q1 *= qr*qw[lane+32];
    k0 *= kr*kw[lane];  k1 *= kr*kw[lane+32];

    float c0 = cosp[s*HD_+lane], c1 = cosp[s*HD_+lane+32];
    float n0 = sinp[s*HD_+lane], n1 = sinp[s*HD_+lane+32];
    float qo0 = (q0*c0 - q1*n0) * 0.125f;
    float qo1 = (q1*c1 + q0*n1) * 0.125f;
    float ko0 =  k0*c0 - k1*n0;
    float ko1 =  k1*c1 + k0*n1;

    size_t o = ((size_t)(b*H_ + h)*S_ + s)*HD_;
    Q[o+lane] = qo0;  Q[o+lane+32] = qo1;
    K[o+lane] = ko0;  K[o+lane+32] = ko1;
    V[o+lane] = v0;   V[o+lane+32] = v1;
}

// ================= TF32 tensor-core flash attention ===============================
// CTA: 128 q-rows x one (b,h). 8 warps, warp owns 16 complete rows (tile 16x64).
// KV tiles of 64 rows. Smem pitches: A-style (pitch%32==4) -> bank 4*gid+tig
// bijective; V (pitch%32==8) -> bank 8*tig+gid bijective. P is warp-private.
#define AQT 128
#define AKT 64
#define AQP 68
#define AKP 68
#define AVP 72
#define APP 68
#define ATTN_SMEM ((AQT*AQP + AKT*AKP + AKT*AVP + AQT*APP) * 4)   // 105472 B

__global__ __launch_bounds__(256, 2)
void attn_mma_kernel(const float* __restrict__ Q,
                     const float* __restrict__ K,
                     const float* __restrict__ V,
                     float* __restrict__ out)
{
    extern __shared__ float sm[];
    float* Qs = sm;
    float* Ks = Qs + AQT*AQP;
    float* Vs = Ks + AKT*AKP;
    float* Ps = Vs + AKT*AVP;

    int bh  = blockIdx.y;
    int qt  = blockIdx.x;
    int tid = threadIdx.x;
    int warp = tid >> 5, lane = tid & 31;
    int gid = lane >> 2, tig = lane & 3;
    int wm = warp * 16;

    // stage Q tile (128 x 64) into smem
    const float* Qb = Q + ((size_t)bh*S_ + qt*AQT)*HD_;
    for (int it = tid; it < AQT*16; it += 256) {
        int r = it >> 4, c4 = (it & 15) * 4;
        cp_async16(&Qs[r*AQP + c4], Qb + r*HD_ + c4);
    }
    CP_COMMIT();

    float m0 = -1e30f, m1 = -1e30f, l0 = 0.f, l1 = 0.f;
    float oacc[8][4];
#pragma unroll
    for (int j = 0; j < 8; j++)
#pragma unroll
        for (int q = 0; q < 4; q++) oacc[j][q] = 0.f;

    const float* Kb0 = K + (size_t)bh*S_*HD_;
    const float* Vb0 = V + (size_t)bh*S_*HD_;

    for (int kt = 0; kt < S_/AKT; kt++) {
        const float* Kb = Kb0 + (size_t)kt*AKT*HD_;
        const float* Vb = Vb0 + (size_t)kt*AKT*HD_;
        for (int it = tid; it < AKT*16; it += 256) {
            int r = it >> 4, c4 = (it & 15) * 4;
            cp_async16(&Ks[r*AKP + c4], Kb + r*HD_ + c4);
            cp_async16(&Vs[r*AVP + c4], Vb + r*HD_ + c4);
        }
        CP_COMMIT();
        CP_WAITALL();
        __syncthreads();

        // ---- S = Q @ K^T : warp rows [wm, wm+16), cols 0..63 -------------------
        float sacc[8][4];
#pragma unroll
        for (int j = 0; j < 8; j++)
#pragma unroll
            for (int q = 0; q < 4; q++) sacc[j][q] = 0.f;

#pragma unroll
        for (int kc = 0; kc < 8; kc++) {
            uint32_t af[4];
            const float* qp = Qs + (wm + gid)*AQP + kc*8 + tig;
            af[0] = f2tf(qp[0]);
            af[1] = f2tf(qp[8*AQP]);
            af[2] = f2tf(qp[4]);
            af[3] = f2tf(qp[8*AQP + 4]);
#pragma unroll
            for (int j = 0; j < 8; j++) {
                uint32_t bf[2];
                const float* kp = Ks + (j*8 + gid)*AKP + kc*8 + tig;
                bf[0] = f2tf(kp[0]);
                bf[1] = f2tf(kp[4]);
                mma_tf32(sacc[j], af, bf);
            }
        }

        // ---- online softmax (warp-local rows gid / gid+8) ----------------------
        float mx0 = -1e30f, mx1 = -1e30f;
#pragma unroll
        for (int j = 0; j < 8; j++) {
            mx0 = fmaxf(mx0, fmaxf(sacc[j][0], sacc[j][1]));
            mx1 = fmaxf(mx1, fmaxf(sacc[j][2], sacc[j][3]));
        }
        mx0 = fmaxf(mx0, __shfl_xor_sync(0xffffffffu, mx0, 1));
        mx0 = fmaxf(mx0, __shfl_xor_sync(0xffffffffu, mx0, 2));
        mx1 = fmaxf(mx1, __shfl_xor_sync(0xffffffffu, mx1, 1));
        mx1 = fmaxf(mx1, __shfl_xor_sync(0xffffffffu, mx1, 2));
        float mn0 = fmaxf(m0, mx0), mn1 = fmaxf(m1, mx1);
        float al0 = __expf(m0 - mn0), al1 = __expf(m1 - mn1);
        float rs0 = 0.f, rs1 = 0.f;
#pragma unroll
        for (int j = 0; j < 8; j++) {
            float p0 = __expf(sacc[j][0] - mn0);
            float p1 = __expf(sacc[j][1] - mn0);
            float p2 = __expf(sacc[j][2] - mn1);
            float p3 = __expf(sacc[j][3] - mn1);
            sacc[j][0] = p0; sacc[j][1] = p1;
            sacc[j][2] = p2; sacc[j][3] = p3;
            rs0 += p0 + p1;  rs1 += p2 + p3;
        }
        rs0 += __shfl_xor_sync(0xffffffffu, rs0, 1);
        rs0 += __shfl_xor_sync(0xffffffffu, rs0, 2);
        rs1 += __shfl_xor_sync(0xffffffffu, rs1, 1);
        rs1 += __shfl_xor_sync(0xffffffffu, rs1, 2);
        l0 = l0*al0 + rs0;  l1 = l1*al1 + rs1;
        m0 = mn0;           m1 = mn1;
#pragma unroll
        for (int j = 0; j < 8; j++) {
            oacc[j][0] *= al0; oacc[j][1] *= al0;
            oacc[j][2] *= al1; oacc[j][3] *= al1;
        }

        // ---- P -> warp-private smem strip --------------------------------------
#pragma unroll
        for (int j = 0; j < 8; j++) {
            float2 a; a.x = sacc[j][0]; a.y = sacc[j][1];
            float2 b; b.x = sacc[j][2]; b.y = sacc[j][3];
            *(float2*)&Ps[(wm + gid    )*APP + j*8 + 2*tig] = a;
            *(float2*)&Ps[(wm + gid + 8)*APP + j*8 + 2*tig] = b;
        }
        __syncwarp();

        // ---- O += P @ V --------------------------------------------------------
#pragma unroll
        for (int kc = 0; kc < 8; kc++) {
            uint32_t af[4];
            const float* pp = Ps + (wm + gid)*APP + kc*8 + tig;
            af[0] = f2tf(pp[0]);
            af[1] = f2tf(pp[8*APP]);
            af[2] = f2tf(pp[4]);
            af[3] = f2tf(pp[8*APP + 4]);
#pragma unroll
            for (int j = 0; j < 8; j++) {
                uint32_t bf[2];
                const float* vp = Vs + (kc*8 + tig)*AVP + j*8 + gid;
                bf[0] = f2tf(vp[0]);
                bf[1] = f2tf(vp[4*AVP]);
                mma_tf32(oacc[j], af, bf);
            }
        }
        __syncthreads();   // all warps done with Ks/Vs before next tile overwrite
    }

    // ---- epilogue: O/l -> g_attn[b][s][h*64+col] -------------------------------
    int b = bh >> 4, h = bh & 15;
    int r0 = qt*AQT + wm + gid;
    float inv0 = 1.f / l0, inv1 = 1.f / l1;
#pragma unroll
    for (int j = 0; j < 8; j++) {
        int col = h*HD_ + j*8 + 2*tig;
        float2 a; a.x = oacc[j][0]*inv0; a.y = oacc[j][1]*inv0;
        float2 c; c.x = oacc[j][2]*inv1; c.y = oacc[j][3]*inv1;
        *(float2*)&out[((size_t)(b*S_ + r0    ))*D_ + col] = a;
        *(float2*)&out[((size_t)(b*S_ + r0 + 8))*D_ + col] = c;
    }
}

// ================= TF32 tensor-core GEMM with fused epilogues =====================
#define GBM 128
#define GBN 128
#define GBK 16
#define AP  20
#define BP  136

__device__ __forceinline__ float gelu_t(float x)
{
    float x3 = x*x*x;
    return 0.5f*x*(1.f + tanhf(0.7978845608028654f*(x + 0.044715f*x3)));
}

// MODE 0: C = acc
// MODE 1: C = res + gate*acc
// MODE 2: C = gelu(acc + bias)
// MODE 3: C = res + gate*(acc + bias)
template <int MODE>
__global__ __launch_bounds__(256)
void mma_gemm(const float* __restrict__ A, const float* __restrict__ Bm,
              float* __restrict__ C, int N, int K,
              const float* __restrict__ res, const float* __restrict__ bias,
              const float* __restrict__ mod, int gate_off)
{
    __shared__ float As[2][GBM*AP];
    __shared__ float Bs[2][GBK*BP];

    int tid  = threadIdx.x;
    int warp = tid >> 5, lane = tid & 31;
    int wm   = (warp >> 2) * 64;
    int wn   = (warp & 3)  * 32;
    int gid  = lane >> 2;
    int tig  = lane & 3;

    const float* Ap = A  + (size_t)blockIdx.y * GBM * K;
    const float* Bp = Bm + blockIdx.x * GBN;

    int ar = tid >> 1;
    int ac = (tid & 1) * 8;
    int bk = tid >> 4;
    int bn = (tid & 15) * 8;

    float acc[4][4][4];
#pragma unroll
    for (int i = 0; i < 4; i++)
#pragma unroll
        for (int j = 0; j < 4; j++)
#pragma unroll
            for (int q = 0; q < 4; q++) acc[i][j][q] = 0.f;

    {
        const float* ag = Ap + (size_t)ar*K + ac;
        cp_async16(&As[0][ar*AP + ac],     ag);
        cp_async16(&As[0][ar*AP + ac + 4], ag + 4);
        const float* bg = Bp + (size_t)bk*N + bn;
        cp_async16(&Bs[0][bk*BP + bn],     bg);
        cp_async16(&Bs[0][bk*BP + bn + 4], bg + 4);
    }
    CP_COMMIT();

    int buf = 0;
    for (int k0 = 0; k0 < K; k0 += GBK) {
        if (k0 + GBK < K) {
            const float* ag = Ap + (size_t)ar*K + (k0 + GBK) + ac;
            cp_async16(&As[buf^1][ar*AP + ac],     ag);
            cp_async16(&As[buf^1][ar*AP + ac + 4], ag + 4);
            const float* bg = Bp + (size_t)(k0 + GBK + bk)*N + bn;
            cp_async16(&Bs[buf^1][bk*BP + bn],     bg);
            cp_async16(&Bs[buf^1][bk*BP + bn + 4], bg + 4);
        }
        CP_COMMIT();
        CP_WAIT1();
        __syncthreads();

        const float* as = As[buf];
        const float* bs = Bs[buf];
#pragma unroll
        for (int kc = 0; kc < GBK; kc += 8) {
            uint32_t af[4][4], bf[4][2];
#pragma unroll
            for (int i = 0; i < 4; i++) {
                int r0 = wm + i*16 + gid;
                af[i][0] = f2tf(as[ r0     *AP + kc + tig]);
                af[i][1] = f2tf(as[(r0 + 8)*AP + kc + tig]);
                af[i][2] = f2tf(as[ r0     *AP + kc + tig + 4]);
                af[i][3] = f2tf(as[(r0 + 8)*AP + kc + tig + 4]);
            }
#pragma unroll
            for (int j = 0; j < 4; j++) {
                int n0 = wn + j*8 + gid;
                bf[j][0] = f2tf(bs[(kc + tig    )*BP + n0]);
                bf[j][1] = f2tf(bs[(kc + tig + 4)*BP + n0]);
            }
#pragma unroll
            for (int i = 0; i < 4; i++)
#pragma unroll
                for (int j = 0; j < 4; j++) {
                    uint32_t afr[4] = {af[i][0], af[i][1], af[i][2], af[i][3]};
                    uint32_t bfr[2] = {bf[j][0], bf[j][1]};
                    mma_tf32(acc[i][j], afr, bfr);
                }
        }
        __syncthreads();
        buf ^= 1;
    }

    int row_base = blockIdx.y*GBM + wm;
    int col_base = blockIdx.x*GBN + wn;
    int bb = (blockIdx.y * GBM) >> 11;
    const float* modb = (MODE == 1 || MODE == 3)
                      ? (mod + bb*SIXD_ + gate_off) : nullptr;
#pragma unroll
    for (int i = 0; i < 4; i++) {
        int r0 = row_base + i*16 + gid;
#pragma unroll
        for (int j = 0; j < 4; j++) {
            int c0 = col_base + j*8 + tig*2;
#pragma unroll
            for (int h = 0; h < 2; h++) {
                int row = r0 + h*8;
                float v0 = acc[i][j][h*2 + 0];
                float v1 = acc[i][j][h*2 + 1];
                if (MODE == 1) {
                    float2 rv = *(const float2*)(res + (size_t)row*N + c0);
                    v0 = rv.x + modb[c0    ]*v0;
                    v1 = rv.y + modb[c0 + 1]*v1;
                } else if (MODE == 2) {
                    v0 = gelu_t(v0 + bias[c0]);
                    v1 = gelu_t(v1 + bias[c0 + 1]);
                } else if (MODE == 3) {
                    float2 rv = *(const float2*)(res + (size_t)row*N + c0);
                    v0 = rv.x + modb[c0    ]*(v0 + bias[c0]);
                    v1 = rv.y + modb[c0 + 1]*(v1 + bias[c0 + 1]);
                }
                float2 st; st.x = v0; st.y = v1;
                *(float2*)(C + (size_t)row*N + c0) = st;
            }
        }
    }
}

// ---------------- launch ---------------------------------------------------------
extern "C" void kernel_launch(void* const* d_in, const int* in_sizes, int n_in,
                              void* d_out, int out_size)
{
    const float* x      = (const float*)d_in[0];
    const float* cosp   = (const float*)d_in[1];
    const float* sinp   = (const float*)d_in[2];
    const float* c      = (const float*)d_in[3];
    const float* n1w    = (const float*)d_in[4];
    const float* Wqkv   = (const float*)d_in[5];
    const float* Wout   = (const float*)d_in[6];
    const float* qw     = (const float*)d_in[7];
    const float* kw     = (const float*)d_in[8];
    const float* n2w    = (const float*)d_in[9];
    const float* W1     = (const float*)d_in[10];
    const float* b1     = (const float*)d_in[11];
    const float* W2     = (const float*)d_in[12];
    const float* b2     = (const float*)d_in[13];
    const float* adaW   = (const float*)d_in[14];
    const float* adab   = (const float*)d_in[15];
    float* out = (float*)d_out;

    float *p_mod, *p_xn, *p_qkv, *p_q, *p_k, *p_v, *p_attn, *p_x2, *p_h;
    cudaGetSymbolAddress((void**)&p_mod,  g_mod);
    cudaGetSymbolAddress((void**)&p_xn,   g_xn);
    cudaGetSymbolAddress((void**)&p_qkv,  g_qkv);
    cudaGetSymbolAddress((void**)&p_q,    g_q);
    cudaGetSymbolAddress((void**)&p_k,    g_k);
    cudaGetSymbolAddress((void**)&p_v,    g_v);
    cudaGetSymbolAddress((void**)&p_attn, g_attn);
    cudaGetSymbolAddress((void**)&p_x2,   g_x2);
    cudaGetSymbolAddress((void**)&p_h,    g_h);

    cudaFuncSetAttribute(attn_mma_kernel,
                         cudaFuncAttributeMaxDynamicSharedMemorySize, ATTN_SMEM);

    // 1. adaLN modulation
    mod_kernel<<<dim3(SIXD_/256, B_), 256>>>(c, adaW, adab, p_mod);
    // 2. LN1 + modulate
    ln_mod_kernel<<<T_, 256>>>(x, n1w, p_mod, p_xn, 0, D_);
    // 3. QKV projection (tf32 mma)
    mma_gemm<0><<<dim3(3*D_/GBN, T_/GBM), 256>>>(p_xn, Wqkv, p_qkv,
                                                 3*D_, D_, nullptr, nullptr,
                                                 nullptr, 0);
    // 4. qk-RMSNorm + RoPE + relayout
    qk_rope_kernel<<<T_, 512>>>(p_qkv, cosp, sinp, qw, kw, p_q, p_k, p_v);
    // 5. attention (tf32 mma flash)
    attn_mma_kernel<<<dim3(S_/AQT, B_*H_), 256, ATTN_SMEM>>>(p_q, p_k, p_v,
                                                             p_attn);
    // 6. out-proj + gated residual (gate = g_msa at 2D)
    mma_gemm<1><<<dim3(D_/GBN, T_/GBM), 256>>>(p_attn, Wout, p_x2,
                                               D_, D_, x, nullptr,
                                               p_mod, 2*D_);
    // 7. LN2 + modulate (shift 3D, scale 4D)
    ln_mod_kernel<<<T_, 256>>>(p_x2, n2w, p_mod, p_xn, 3*D_, 4*D_);
    // 8. MLP up + gelu
    mma_gemm<2><<<dim3(DFF_/GBN, T_/GBM), 256>>>(p_xn, W1, p_h,
                                                 DFF_, D_, nullptr, b1,
                                                 nullptr, 0);
    // 9. MLP down + gated residual (gate = g_mlp at 5D)
    mma_gemm<3><<<dim3(D_/GBN, T_/GBM), 256>>>(p_h, W2, out,
                                               D_, DFF_, p_x2, b2,
                                               p_mod, 5*D_);
}